// round 14
// baseline (speedup 1.0000x reference)
#include <cuda_runtime.h>
#include <cuda_bf16.h>
#include <cuda_fp16.h>
#include <math.h>
#include <stdint.h>

#define NNODES 50000
#define EMAXE  800000
#define IN_F   256
#define HH     4
#define DD     64
#define HD     256
#define HD2    512
#define NEG_SLOPE 0.2f

// ---------------- scratch (static __device__, no allocs) ----------------
__device__ __align__(16) __half g_feat1[NNODES * HD];
__device__ __align__(16) __half g_feat2[NNODES * HD];
__device__ __align__(16) float g_el1[NNODES * HH], g_er1[NNODES * HH];
__device__ __align__(16) float g_el2[NNODES * HH], g_er2[NNODES * HH];

__device__ __align__(16) __nv_bfloat16 g_h_hi[NNODES * IN_F],  g_h_lo[NNODES * IN_F];
__device__ __align__(16) __nv_bfloat16 g_semh[NNODES * HD2],   g_seml[NNODES * HD2];
__device__ __align__(16) __nv_bfloat16 g_wgh[HD2 * IN_F], g_wgl[HD2 * IN_F];
__device__ __align__(16) __nv_bfloat16 g_wfch[HD * HD2],  g_wfcl[HD * HD2];

__device__ int g_cnt1[NNODES],  g_cnt2[NNODES];
__device__ int g_off1[NNODES + 1], g_off2[NNODES + 1];
__device__ int g_cur1[NNODES],  g_cur2[NNODES];
__device__ int g_csr1[EMAXE],   g_csr2[EMAXE];

// ================= helpers =================
__device__ __forceinline__ uint32_t smem_u32(const void* p) {
    uint32_t a;
    asm("{ .reg .u64 t; cvta.to.shared.u64 t, %1; cvt.u32.u64 %0, t; }" : "=r"(a) : "l"(p));
    return a;
}

#define LDSM_X4(r0, r1, r2, r3, addr) \
    asm volatile("ldmatrix.sync.aligned.m8n8.x4.shared.b16 {%0,%1,%2,%3}, [%4];" \
                 : "=r"(r0), "=r"(r1), "=r"(r2), "=r"(r3) : "r"(addr))

#define MMA_16816(d, a0, a1, a2, a3, b0, b1) \
    asm volatile("mma.sync.aligned.m16n8k16.row.col.f32.bf16.bf16.f32 " \
                 "{%0,%1,%2,%3}, {%4,%5,%6,%7}, {%8,%9}, {%0,%1,%2,%3};" \
                 : "+f"((d)[0]), "+f"((d)[1]), "+f"((d)[2]), "+f"((d)[3]) \
                 : "r"(a0), "r"(a1), "r"(a2), "r"(a3), "r"(b0), "r"(b1))

#define CP16(dst, src) \
    asm volatile("cp.async.cg.shared.global [%0], [%1], 16;" :: "r"(dst), "l"(src))
#define CP_COMMIT() asm volatile("cp.async.commit_group;" ::: "memory")
#define CP_WAITG1() asm volatile("cp.async.wait_group 1;" ::: "memory")

// XOR swizzle for 64B rows: byte offset within one 128x32bf16 tile.
__device__ __forceinline__ uint32_t swz(uint32_t row, uint32_t cb) {
    return row * 64 + ((((cb >> 4) ^ ((row >> 1) & 3)) << 4) | (cb & 15));
}

// split one float4 into bf16 hi/lo uint2 pairs
__device__ __forceinline__ void split4(const float* __restrict__ x,
                                       __nv_bfloat16* __restrict__ hi,
                                       __nv_bfloat16* __restrict__ lo, int i)
{
    float4 v = ((const float4*)x)[i];
    float vv[4] = {v.x, v.y, v.z, v.w};
    __align__(8) __nv_bfloat16 hb[4], lb[4];
#pragma unroll
    for (int k = 0; k < 4; k++) {
        hb[k] = __float2bfloat16(vv[k]);
        lb[k] = __float2bfloat16(vv[k] - __bfloat162float(hb[k]));
    }
    ((uint2*)hi)[i] = *(uint2*)hb;
    ((uint2*)lo)[i] = *(uint2*)lb;
}

// ================= K1: zero counts + weight splits =================
// blocks: [0,ZB) zero, [ZB,ZB+64) Wg1, [..+64) Wg2, [..+128) Wfc
__global__ void pre1_kernel(const float* __restrict__ Wg1, const float* __restrict__ Wg2,
                            const float* __restrict__ Wfc, int Nn, int ZB)
{
    int b = blockIdx.x;
    int t = threadIdx.x;
    if (b < ZB) {
        int i = b * 256 + t;
        if (i < Nn) { g_cnt1[i] = 0; g_cnt2[i] = 0; }
        return;
    }
    b -= ZB;
    if (b < 64)  { split4(Wg1, g_wgh, g_wgl, b * 256 + t); return; }
    b -= 64;
    if (b < 64)  { split4(Wg2, g_wgh + HD * IN_F, g_wgl + HD * IN_F, b * 256 + t); return; }
    b -= 64;
    split4(Wfc, g_wfch, g_wfcl, b * 256 + t);
}

// ================= K2: h split + both hists =================
__global__ void pre2_kernel(const float* __restrict__ h,
                            const int* __restrict__ dst1, const int* __restrict__ dst2,
                            int HB, int E1, int E2, int H1B)
{
    int b = blockIdx.x;
    int t = threadIdx.x;
    if (b < HB) { split4(h, g_h_hi, g_h_lo, b * 256 + t); return; }
    b -= HB;
    if (b < H1B) {
        int e = b * 256 + t;
        if (e < E1) atomicAdd(&g_cnt1[dst1[e]], 1);
        return;
    }
    b -= H1B;
    int e = b * 256 + t;
    if (e < E2) atomicAdd(&g_cnt2[dst2[e]], 1);
}

// ================= K3: single-kernel scan (2 blocks x 1024 threads) ==========
__global__ void scan_kernel(int Nn, int E1, int E2)
{
    __shared__ int s[1024];
    const int rel = blockIdx.x;
    const int* cnt = rel ? g_cnt2 : g_cnt1;
    int* off = rel ? g_off2 : g_off1;
    int* cur = rel ? g_cur2 : g_cur1;
    const int E = rel ? E2 : E1;
    const int tid = threadIdx.x;
    int running = 0;

    for (int base = 0; base < Nn; base += 4096) {
        int i0 = base + tid * 4;
        int4 v = make_int4(0, 0, 0, 0);
        if (i0 + 3 < Nn) {
            v = *(const int4*)(cnt + i0);
        } else {
            if (i0 + 0 < Nn) v.x = cnt[i0 + 0];
            if (i0 + 1 < Nn) v.y = cnt[i0 + 1];
            if (i0 + 2 < Nn) v.z = cnt[i0 + 2];
            if (i0 + 3 < Nn) v.w = cnt[i0 + 3];
        }
        int tsum = v.x + v.y + v.z + v.w;
        s[tid] = tsum;
        __syncthreads();
#pragma unroll
        for (int o = 1; o < 1024; o <<= 1) {
            int tv = (tid >= o) ? s[tid - o] : 0;
            __syncthreads();
            s[tid] += tv;
            __syncthreads();
        }
        int excl = running + s[tid] - tsum;
        int total = s[1023];
        int o0 = excl, o1 = o0 + v.x, o2 = o1 + v.y, o3 = o2 + v.z;
        if (i0 + 3 < Nn) {
            *(int4*)(off + i0) = make_int4(o0, o1, o2, o3);
            *(int4*)(cur + i0) = make_int4(o0, o1, o2, o3);
        } else {
            if (i0 + 0 < Nn) { off[i0 + 0] = o0; cur[i0 + 0] = o0; }
            if (i0 + 1 < Nn) { off[i0 + 1] = o1; cur[i0 + 1] = o1; }
            if (i0 + 2 < Nn) { off[i0 + 2] = o2; cur[i0 + 2] = o2; }
            if (i0 + 3 < Nn) { off[i0 + 3] = o3; cur[i0 + 3] = o3; }
        }
        running += total;
        __syncthreads();
    }
    if (tid == 0) off[Nn] = E;
}

// ================= K4: fill (both relations via grid.y) =================
__global__ void fill_kernel(const int* __restrict__ src1, const int* __restrict__ dst1,
                            const int* __restrict__ src2, const int* __restrict__ dst2,
                            int E1, int E2)
{
    int e = blockIdx.x * blockDim.x + threadIdx.x;
    if (blockIdx.y == 0) {
        if (e < E1) { int pos = atomicAdd(&g_cur1[dst1[e]], 1); g_csr1[pos] = src1[e]; }
    } else {
        if (e < E2) { int pos = atomicAdd(&g_cur2[dst2[e]], 1); g_csr2[pos] = src2[e]; }
    }
}

// ================= split-bf16 GEMM via mma.sync, cp.async 3-stage, swizzled ====
#define GK 32
#define TB 8192
#define STG (4 * TB)
#define NSTG 3
#define GSM_TOTAL (NSTG * STG)     // 98304

__device__ __forceinline__ void load_chunk(uint32_t sbs,
    const __nv_bfloat16* __restrict__ Ah, const __nv_bfloat16* __restrict__ Al,
    const __nv_bfloat16* __restrict__ Bh, const __nv_bfloat16* __restrict__ Bl,
    int m0, int n0, int M, int K, int kc, int tid)
{
#pragma unroll
    for (int u = 0; u < 2; u++) {
        int c = tid * 2 + u;
        int row = c >> 2, cc = c & 3;
        uint32_t soff = swz((uint32_t)row, (uint32_t)cc * 16);
        int m = m0 + row;
        if (m < M) {
            size_t ga = (size_t)m * K + kc + cc * 8;
            CP16(sbs + soff,      (const char*)(Ah + ga));
            CP16(sbs + TB + soff, (const char*)(Al + ga));
        }
        size_t gb = (size_t)(n0 + row) * K + kc + cc * 8;
        CP16(sbs + 2 * TB + soff, (const char*)(Bh + gb));
        CP16(sbs + 3 * TB + soff, (const char*)(Bl + gb));
    }
}

__global__ void __launch_bounds__(256, 2)
mma_gemm_kernel(const __nv_bfloat16* __restrict__ Ah, const __nv_bfloat16* __restrict__ Al,
                const __nv_bfloat16* __restrict__ Bh, const __nv_bfloat16* __restrict__ Bl,
                int M, int K, int mode,
                float* __restrict__ C,
                __half* __restrict__ feat1, __half* __restrict__ feat2,
                const float* __restrict__ al1v, const float* __restrict__ ar1v,
                const float* __restrict__ al2v, const float* __restrict__ ar2v,
                float* __restrict__ el1, float* __restrict__ er1,
                float* __restrict__ el2, float* __restrict__ er2,
                const float* __restrict__ bias)
{
    extern __shared__ __align__(16) char dsm[];
    __shared__ float sAlv[128], sArv[128];
    __shared__ float sEl[256], sEr[256];

    const uint32_t sb = smem_u32(dsm);
    const int tid = threadIdx.x;
    const int lane = tid & 31;
    const int wid = tid >> 5;
    const int wm = wid >> 2;
    const int wn = wid & 3;
    const int m0 = blockIdx.y * 128, n0 = blockIdx.x * 128;

    const int rel = (n0 >= HD) ? 1 : 0;
    const int ncol0 = n0 & (HD - 1);
    const int h0 = ncol0 >> 6;

    if (mode == 0 && tid < 128) {
        const float* alsel = rel ? al2v : al1v;
        const float* arsel = rel ? ar2v : ar1v;
        sAlv[tid] = alsel[h0 * 64 + tid];
        sArv[tid] = arsel[h0 * 64 + tid];
    }
    sEl[tid] = 0.f; sEr[tid] = 0.f;

    float acc[4][4][4];
#pragma unroll
    for (int i = 0; i < 4; i++)
#pragma unroll
        for (int j = 0; j < 4; j++)
#pragma unroll
            for (int r = 0; r < 4; r++) acc[i][j][r] = 0.f;

    const int a_row = (lane & 15);
    const int a_kof = (lane >> 4) << 3;
    const int b_row = (lane & 7) + ((lane >> 4) << 3);
    const int b_kof = ((lane >> 3) & 1) << 3;

    const int nchunk = K / GK;

    // preload stages 0,1
    load_chunk(sb, Ah, Al, Bh, Bl, m0, n0, M, K, 0, tid);
    CP_COMMIT();
    if (nchunk > 1)
        load_chunk(sb + STG, Ah, Al, Bh, Bl, m0, n0, M, K, GK, tid);
    CP_COMMIT();

    int st = 0;                     // stage of chunk c
    for (int c = 0; c < nchunk; c++) {
        CP_WAITG1();                // chunk c's group complete
        __syncthreads();            // all warps done with stage (c+2)%3's previous use
        if (c + 2 < nchunk) {
            int st2 = st + 2; if (st2 >= NSTG) st2 -= NSTG;
            load_chunk(sb + st2 * STG, Ah, Al, Bh, Bl, m0, n0, M, K, (c + 2) * GK, tid);
        }
        CP_COMMIT();

        const uint32_t sbs = sb + st * STG;
        const uint32_t sbAh = sbs, sbAl = sbs + TB, sbBh = sbs + 2 * TB, sbBl = sbs + 3 * TB;
#pragma unroll
        for (int k0 = 0; k0 < GK; k0 += 16) {
            uint32_t bh[4][2], bl[4][2];
#pragma unroll
            for (int g = 0; g < 2; g++) {
                int nrow = wn * 32 + g * 16 + b_row;
                uint32_t ba = swz((uint32_t)nrow, (uint32_t)(k0 + b_kof) * 2);
                uint32_t r0, r1, r2, r3;
                LDSM_X4(r0, r1, r2, r3, sbBh + ba);
                bh[g * 2][0] = r0; bh[g * 2][1] = r1;
                bh[g * 2 + 1][0] = r2; bh[g * 2 + 1][1] = r3;
                LDSM_X4(r0, r1, r2, r3, sbBl + ba);
                bl[g * 2][0] = r0; bl[g * 2][1] = r1;
                bl[g * 2 + 1][0] = r2; bl[g * 2 + 1][1] = r3;
            }
#pragma unroll
            for (int im = 0; im < 4; im++) {
                int arow = wm * 64 + im * 16 + a_row;
                uint32_t aa = swz((uint32_t)arow, (uint32_t)(k0 + a_kof) * 2);
                uint32_t ah0, ah1, ah2, ah3, al0, al1, al2, al3;
                LDSM_X4(ah0, ah1, ah2, ah3, sbAh + aa);
                LDSM_X4(al0, al1, al2, al3, sbAl + aa);
#pragma unroll
                for (int in = 0; in < 4; in++) {
                    MMA_16816(acc[im][in], ah0, ah1, ah2, ah3, bh[in][0], bh[in][1]);
                    MMA_16816(acc[im][in], ah0, ah1, ah2, ah3, bl[in][0], bl[in][1]);
                    MMA_16816(acc[im][in], al0, al1, al2, al3, bh[in][0], bh[in][1]);
                }
            }
        }
        if (++st == NSTG) st = 0;
    }

    // ---- epilogue ----
    if (mode == 0) {
        __half* Cf = rel ? feat2 : feat1;
        const int hl = wn >> 1;
#pragma unroll
        for (int im = 0; im < 4; im++) {
            int r0l = wm * 64 + im * 16 + (lane >> 2);
            float e0 = 0.f, e1 = 0.f, q0 = 0.f, q1 = 0.f;
#pragma unroll
            for (int in = 0; in < 4; in++) {
                int ct = wn * 32 + in * 8 + (lane & 3) * 2;
                float a0 = sAlv[ct], a1 = sAlv[ct + 1];
                float p0 = sArv[ct], p1 = sArv[ct + 1];
                e0 += acc[im][in][0] * a0 + acc[im][in][1] * a1;
                q0 += acc[im][in][0] * p0 + acc[im][in][1] * p1;
                e1 += acc[im][in][2] * a0 + acc[im][in][3] * a1;
                q1 += acc[im][in][2] * p0 + acc[im][in][3] * p1;

                int row0 = m0 + r0l;
                int col  = ncol0 + ct;
                if (row0 < M)
                    *(__half2*)(Cf + (size_t)row0 * HD + col) =
                        __floats2half2_rn(acc[im][in][0], acc[im][in][1]);
                if (row0 + 8 < M)
                    *(__half2*)(Cf + (size_t)(row0 + 8) * HD + col) =
                        __floats2half2_rn(acc[im][in][2], acc[im][in][3]);
            }
            atomicAdd(&sEl[r0l * 2 + hl], e0);
            atomicAdd(&sEr[r0l * 2 + hl], q0);
            atomicAdd(&sEl[(r0l + 8) * 2 + hl], e1);
            atomicAdd(&sEr[(r0l + 8) * 2 + hl], q1);
        }
        __syncthreads();
        if (tid < 128) {
            int m = m0 + tid;
            if (m < M) {
                float* elo = rel ? el2 : el1;
                float* ero = rel ? er2 : er1;
                elo[(size_t)m * HH + h0 + 0] = sEl[tid * 2 + 0];
                elo[(size_t)m * HH + h0 + 1] = sEl[tid * 2 + 1];
                ero[(size_t)m * HH + h0 + 0] = sEr[tid * 2 + 0];
                ero[(size_t)m * HH + h0 + 1] = sEr[tid * 2 + 1];
            }
        }
    } else {
#pragma unroll
        for (int im = 0; im < 4; im++) {
#pragma unroll
            for (int in = 0; in < 4; in++) {
                int row0 = m0 + wm * 64 + im * 16 + (lane >> 2);
                int col  = n0 + wn * 32 + in * 8 + (lane & 3) * 2;
                float bx = bias[col], by = bias[col + 1];
                if (row0 < M)
                    *(float2*)(C + (size_t)row0 * HD + col) =
                        make_float2(acc[im][in][0] + bx, acc[im][in][1] + by);
                if (row0 + 8 < M)
                    *(float2*)(C + (size_t)(row0 + 8) * HD + col) =
                        make_float2(acc[im][in][2] + bx, acc[im][in][3] + by);
            }
        }
    }
}

// ================= fused GAT aggregate: warp per dst node, 2 passes, fp16 gather ====
__global__ void gat_aggregate_kernel(const float* __restrict__ b1v,
                                     const float* __restrict__ b2v, int Nn)
{
    int n = (blockIdx.x * blockDim.x + threadIdx.x) >> 5;
    int lane = threadIdx.x & 31;
    if (n >= Nn) return;
    const int relv = blockIdx.y;
    const int* off = relv ? g_off2 : g_off1;
    const int* csr = relv ? g_csr2 : g_csr1;
    const float* el = relv ? g_el2 : g_el1;
    const float* er = relv ? g_er2 : g_er1;
    const __half* feat = relv ? g_feat2 : g_feat1;
    const float* bias = relv ? b2v : b1v;
    const int rel_off = relv ? HD : 0;

    const int beg = off[n], end = off[n + 1];
    float4 er4 = *(const float4*)(er + n * HH);

    // pass 1: denom (no max subtraction; |e| small so exp is safe)
    float4 ds = make_float4(0.f, 0.f, 0.f, 0.f);
    for (int k = beg + lane; k < end; k += 32) {
        int s = csr[k];
        float4 l = *(const float4*)(el + s * HH);
        float4 e;
        e.x = l.x + er4.x; e.x = e.x > 0.f ? e.x : NEG_SLOPE * e.x;
        e.y = l.y + er4.y; e.y = e.y > 0.f ? e.y : NEG_SLOPE * e.y;
        e.z = l.z + er4.z; e.z = e.z > 0.f ? e.z : NEG_SLOPE * e.z;
        e.w = l.w + er4.w; e.w = e.w > 0.f ? e.w : NEG_SLOPE * e.w;
        ds.x += __expf(e.x); ds.y += __expf(e.y);
        ds.z += __expf(e.z); ds.w += __expf(e.w);
    }
#pragma unroll
    for (int o = 16; o; o >>= 1) {
        ds.x += __shfl_xor_sync(0xffffffffu, ds.x, o);
        ds.y += __shfl_xor_sync(0xffffffffu, ds.y, o);
        ds.z += __shfl_xor_sync(0xffffffffu, ds.z, o);
        ds.w += __shfl_xor_sync(0xffffffffu, ds.w, o);
    }

    const int head = lane >> 3;
    const float dh   = head == 0 ? ds.x : head == 1 ? ds.y : head == 2 ? ds.z : ds.w;
    const float erh  = head == 0 ? er4.x: head == 1 ? er4.y: head == 2 ? er4.z: er4.w;
    const float invd = 1.0f / dh;

    float acc[8];
#pragma unroll
    for (int i = 0; i < 8; i++) acc[i] = 0.f;

    // pass 2: weighted fp16 gather, deeper MLP via unroll 4
    for (int base = beg; base < end; base += 32) {
        int myidx = (base + lane < end) ? csr[base + lane] : 0;
        int cnt = min(32, end - base);
#pragma unroll 4
        for (int j = 0; j < cnt; j++) {
            int s = __shfl_sync(0xffffffffu, myidx, j);
            float e = el[s * HH + head] + erh;
            e = e > 0.f ? e : NEG_SLOPE * e;
            float alpha = __expf(e) * invd;
            uint4 raw = *(const uint4*)(feat + (size_t)s * HD + lane * 8);
            float2 f0 = __half22float2(*(__half2*)&raw.x);
            float2 f1 = __half22float2(*(__half2*)&raw.y);
            float2 f2 = __half22float2(*(__half2*)&raw.z);
            float2 f3 = __half22float2(*(__half2*)&raw.w);
            acc[0] = fmaf(f0.x, alpha, acc[0]);
            acc[1] = fmaf(f0.y, alpha, acc[1]);
            acc[2] = fmaf(f1.x, alpha, acc[2]);
            acc[3] = fmaf(f1.y, alpha, acc[3]);
            acc[4] = fmaf(f2.x, alpha, acc[4]);
            acc[5] = fmaf(f2.y, alpha, acc[5]);
            acc[6] = fmaf(f3.x, alpha, acc[6]);
            acc[7] = fmaf(f3.y, alpha, acc[7]);
        }
    }

    float4 bo0 = *(const float4*)(bias + lane * 8);
    float4 bo1 = *(const float4*)(bias + lane * 8 + 4);
    float w[8];
    w[0] = acc[0] + bo0.x; w[1] = acc[1] + bo0.y; w[2] = acc[2] + bo0.z; w[3] = acc[3] + bo0.w;
    w[4] = acc[4] + bo1.x; w[5] = acc[5] + bo1.y; w[6] = acc[6] + bo1.z; w[7] = acc[7] + bo1.w;

    __align__(16) __nv_bfloat16 hb[8], lb[8];
#pragma unroll
    for (int i = 0; i < 8; i++) {
        hb[i] = __float2bfloat16(w[i]);
        lb[i] = __float2bfloat16(w[i] - __bfloat162float(hb[i]));
    }
    size_t didx = (size_t)n * HD2 + rel_off + lane * 8;
    *(uint4*)(g_semh + didx) = *(uint4*)hb;
    *(uint4*)(g_seml + didx) = *(uint4*)lb;
}

// ================= launch =================
static inline int ceil_div(int a, int b) { return (a + b - 1) / b; }

extern "C" void kernel_launch(void* const* d_in, const int* in_sizes, int n_in,
                              void* d_out, int out_size)
{
    const float* h    = (const float*)d_in[0];
    const float* Wg1  = (const float*)d_in[1];
    const float* al1  = (const float*)d_in[2];
    const float* ar1  = (const float*)d_in[3];
    const float* b1   = (const float*)d_in[4];
    const float* Wg2  = (const float*)d_in[5];
    const float* al2  = (const float*)d_in[6];
    const float* ar2  = (const float*)d_in[7];
    const float* b2   = (const float*)d_in[8];
    const float* Wfc  = (const float*)d_in[9];
    const float* bfc  = (const float*)d_in[10];
    const int*   src1 = (const int*)d_in[11];
    const int*   dst1 = (const int*)d_in[12];
    const int*   src2 = (const int*)d_in[13];
    const int*   dst2 = (const int*)d_in[14];
    float* out = (float*)d_out;

    const int Nn = in_sizes[0] / IN_F;
    const int E1 = in_sizes[11];
    const int E2 = in_sizes[13];

    __half *feat1, *feat2;
    float *el1, *er1, *el2, *er2;
    __nv_bfloat16 *hhi, *hlo, *semh, *seml, *wgh, *wgl, *wfch, *wfcl;
    cudaGetSymbolAddress((void**)&feat1, g_feat1);
    cudaGetSymbolAddress((void**)&feat2, g_feat2);
    cudaGetSymbolAddress((void**)&el1,   g_el1);
    cudaGetSymbolAddress((void**)&er1,   g_er1);
    cudaGetSymbolAddress((void**)&el2,   g_el2);
    cudaGetSymbolAddress((void**)&er2,   g_er2);
    cudaGetSymbolAddress((void**)&hhi,   g_h_hi);
    cudaGetSymbolAddress((void**)&hlo,   g_h_lo);
    cudaGetSymbolAddress((void**)&semh,  g_semh);
    cudaGetSymbolAddress((void**)&seml,  g_seml);
    cudaGetSymbolAddress((void**)&wgh,   g_wgh);
    cudaGetSymbolAddress((void**)&wgl,   g_wgl);
    cudaGetSymbolAddress((void**)&wfch,  g_wfch);
    cudaGetSymbolAddress((void**)&wfcl,  g_wfcl);

    cudaFuncSetAttribute(mma_gemm_kernel, cudaFuncAttributeMaxDynamicSharedMemorySize, GSM_TOTAL);

    // --- K1: zero counts + weight splits ---
    const int ZB = ceil_div(Nn, 256);
    pre1_kernel<<<ZB + 64 + 64 + 128, 256>>>(Wg1, Wg2, Wfc, Nn, ZB);

    // --- K2: h split + both hists ---
    const int HB = Nn * IN_F / 4 / 256;
    const int H1B = ceil_div(E1, 256);
    const int H2B = ceil_div(E2, 256);
    pre2_kernel<<<HB + H1B + H2B, 256>>>(h, dst1, dst2, HB, E1, E2, H1B);

    // --- K3: scan (both relations) ---
    scan_kernel<<<2, 1024>>>(Nn, E1, E2);

    // --- K4: fill ---
    {
        const int Emax = E1 > E2 ? E1 : E2;
        dim3 g(ceil_div(Emax, 256), 2);
        fill_kernel<<<g, 256>>>(src1, dst1, src2, dst2, E1, E2);
    }

    // --- K5: fused projection GEMM (both relations), el/er in epilogue ---
    {
        dim3 grid(4, ceil_div(Nn, 128));
        mma_gemm_kernel<<<grid, 256, GSM_TOTAL>>>(hhi, hlo, wgh, wgl, Nn, IN_F, 0,
                                                  nullptr, feat1, feat2,
                                                  al1, ar1, al2, ar2,
                                                  el1, er1, el2, er2, nullptr);
    }
    // --- K6: fused softmax + aggregate ---
    {
        dim3 grid(ceil_div(Nn * 32, 256), 2);
        gat_aggregate_kernel<<<grid, 256>>>(b1, b2, Nn);
    }
    // --- K7: FC GEMM ---
    {
        dim3 grid(2, ceil_div(Nn, 128));
        mma_gemm_kernel<<<grid, 256, GSM_TOTAL>>>(semh, seml, wfch, wfcl, Nn, HD2, 1,
                                                  out, nullptr, nullptr,
                                                  nullptr, nullptr, nullptr, nullptr,
                                                  nullptr, nullptr, nullptr, nullptr, bfc);
    }
}

// round 16
// speedup vs baseline: 1.0878x; 1.0878x over previous
#include <cuda_runtime.h>
#include <cuda_bf16.h>
#include <cuda_fp16.h>
#include <math.h>
#include <stdint.h>

#define NNODES 50000
#define EMAXE  800000
#define IN_F   256
#define HH     4
#define DD     64
#define HD     256
#define HD2    512
#define NEG_SLOPE 0.2f

// ---------------- scratch (static __device__, no allocs) ----------------
__device__ __align__(16) __half g_feat1[NNODES * HD];
__device__ __align__(16) __half g_feat2[NNODES * HD];
__device__ __align__(16) float g_el1[NNODES * HH], g_er1[NNODES * HH];
__device__ __align__(16) float g_el2[NNODES * HH], g_er2[NNODES * HH];

__device__ __align__(16) __nv_bfloat16 g_h_hi[NNODES * IN_F],  g_h_lo[NNODES * IN_F];
__device__ __align__(16) __nv_bfloat16 g_semh[NNODES * HD2],   g_seml[NNODES * HD2];
__device__ __align__(16) __nv_bfloat16 g_wgh[HD2 * IN_F], g_wgl[HD2 * IN_F];
__device__ __align__(16) __nv_bfloat16 g_wfch[HD * HD2],  g_wfcl[HD * HD2];

__device__ int g_cnt1[NNODES],  g_cnt2[NNODES];
__device__ int g_off1[NNODES + 1], g_off2[NNODES + 1];
__device__ int g_cur1[NNODES],  g_cur2[NNODES];
__device__ int g_csr1[EMAXE],   g_csr2[EMAXE];
__device__ int g_part1[64],     g_part2[64];

// ================= helpers =================
__device__ __forceinline__ uint32_t smem_u32(const void* p) {
    uint32_t a;
    asm("{ .reg .u64 t; cvta.to.shared.u64 t, %1; cvt.u32.u64 %0, t; }" : "=r"(a) : "l"(p));
    return a;
}

#define LDSM_X4(r0, r1, r2, r3, addr) \
    asm volatile("ldmatrix.sync.aligned.m8n8.x4.shared.b16 {%0,%1,%2,%3}, [%4];" \
                 : "=r"(r0), "=r"(r1), "=r"(r2), "=r"(r3) : "r"(addr))

#define MMA_16816(d, a0, a1, a2, a3, b0, b1) \
    asm volatile("mma.sync.aligned.m16n8k16.row.col.f32.bf16.bf16.f32 " \
                 "{%0,%1,%2,%3}, {%4,%5,%6,%7}, {%8,%9}, {%0,%1,%2,%3};" \
                 : "+f"((d)[0]), "+f"((d)[1]), "+f"((d)[2]), "+f"((d)[3]) \
                 : "r"(a0), "r"(a1), "r"(a2), "r"(a3), "r"(b0), "r"(b1))

#define CP16(dst, src) \
    asm volatile("cp.async.cg.shared.global [%0], [%1], 16;" :: "r"(dst), "l"(src))
#define CP_COMMIT() asm volatile("cp.async.commit_group;" ::: "memory")
#define CP_WAIT1()  asm volatile("cp.async.wait_group 1;" ::: "memory")

// XOR swizzle for 64B rows: byte offset within one 128x32bf16 tile.
__device__ __forceinline__ uint32_t swz(uint32_t row, uint32_t cb) {
    return row * 64 + ((((cb >> 4) ^ ((row >> 1) & 3)) << 4) | (cb & 15));
}

// split one float4 into bf16 hi/lo uint2 pairs
__device__ __forceinline__ void split4(const float* __restrict__ x,
                                       __nv_bfloat16* __restrict__ hi,
                                       __nv_bfloat16* __restrict__ lo, int i)
{
    float4 v = ((const float4*)x)[i];
    float vv[4] = {v.x, v.y, v.z, v.w};
    __align__(8) __nv_bfloat16 hb[4], lb[4];
#pragma unroll
    for (int k = 0; k < 4; k++) {
        hb[k] = __float2bfloat16(vv[k]);
        lb[k] = __float2bfloat16(vv[k] - __bfloat162float(hb[k]));
    }
    ((uint2*)hi)[i] = *(uint2*)hb;
    ((uint2*)lo)[i] = *(uint2*)lb;
}

// ================= K1: zero counts + weight splits =================
__global__ void pre1_kernel(const float* __restrict__ Wg1, const float* __restrict__ Wg2,
                            const float* __restrict__ Wfc, int Nn, int ZB)
{
    int b = blockIdx.x;
    int t = threadIdx.x;
    if (b < ZB) {
        int i = b * 256 + t;
        if (i < Nn) { g_cnt1[i] = 0; g_cnt2[i] = 0; }
        return;
    }
    b -= ZB;
    if (b < 64)  { split4(Wg1, g_wgh, g_wgl, b * 256 + t); return; }
    b -= 64;
    if (b < 64)  { split4(Wg2, g_wgh + HD * IN_F, g_wgl + HD * IN_F, b * 256 + t); return; }
    b -= 64;
    split4(Wfc, g_wfch, g_wfcl, b * 256 + t);
}

// ================= K2: h split + both hists =================
__global__ void pre2_kernel(const float* __restrict__ h,
                            const int* __restrict__ dst1, const int* __restrict__ dst2,
                            int HB, int E1, int E2, int H1B)
{
    int b = blockIdx.x;
    int t = threadIdx.x;
    if (b < HB) { split4(h, g_h_hi, g_h_lo, b * 256 + t); return; }
    b -= HB;
    if (b < H1B) {
        int e = b * 256 + t;
        if (e < E1) atomicAdd(&g_cnt1[dst1[e]], 1);
        return;
    }
    b -= H1B;
    int e = b * 256 + t;
    if (e < E2) atomicAdd(&g_cnt2[dst2[e]], 1);
}

// ================= scan chain (proven R9 version, gridDim.y = relation) ========
__global__ void partial_kernel(int Nn)
{
    __shared__ int sred[256];
    const int* cnt = blockIdx.y ? g_cnt2 : g_cnt1;
    int* part = blockIdx.y ? g_part2 : g_part1;
    int tid = threadIdx.x;
    int base = blockIdx.x * 1024;
    int sum = 0;
#pragma unroll
    for (int j = 0; j < 4; j++) {
        int i = base + j * 256 + tid;
        if (i < Nn) sum += cnt[i];
    }
    sred[tid] = sum;
    __syncthreads();
#pragma unroll
    for (int o = 128; o; o >>= 1) {
        if (tid < o) sred[tid] += sred[tid + o];
        __syncthreads();
    }
    if (tid == 0) part[blockIdx.x] = sred[0];
}

__global__ void top_scan_kernel(int nb)
{
    int* part = blockIdx.x ? g_part2 : g_part1;
    if (threadIdx.x == 0) {
        int run = 0;
        for (int i = 0; i < nb; i++) { int v = part[i]; part[i] = run; run += v; }
    }
}

__global__ void final_scan_kernel(int Nn, int E1, int E2)
{
    __shared__ int s[256];
    const int* cnt = blockIdx.y ? g_cnt2 : g_cnt1;
    const int* part = blockIdx.y ? g_part2 : g_part1;
    int* off = blockIdx.y ? g_off2 : g_off1;
    int* cur = blockIdx.y ? g_cur2 : g_cur1;
    int E = blockIdx.y ? E2 : E1;
    int tid = threadIdx.x;
    int base = blockIdx.x * 1024;
    int v[4]; int loc = 0;
#pragma unroll
    for (int j = 0; j < 4; j++) {
        int i = base + tid * 4 + j;
        v[j] = (i < Nn) ? cnt[i] : 0;
        loc += v[j];
    }
    s[tid] = loc;
    __syncthreads();
#pragma unroll
    for (int o = 1; o < 256; o <<= 1) {
        int t = (tid >= o) ? s[tid - o] : 0;
        __syncthreads();
        s[tid] += t;
        __syncthreads();
    }
    int run = part[blockIdx.x] + s[tid] - loc;
#pragma unroll
    for (int j = 0; j < 4; j++) {
        int i = base + tid * 4 + j;
        if (i < Nn) { off[i] = run; cur[i] = run; run += v[j]; }
    }
    if (blockIdx.x == 0 && tid == 0) off[Nn] = E;
}

__global__ void fill_kernel(const int* __restrict__ src1, const int* __restrict__ dst1,
                            const int* __restrict__ src2, const int* __restrict__ dst2,
                            int E1, int E2)
{
    int e = blockIdx.x * blockDim.x + threadIdx.x;
    if (blockIdx.y == 0) {
        if (e < E1) { int pos = atomicAdd(&g_cur1[dst1[e]], 1); g_csr1[pos] = src1[e]; }
    } else {
        if (e < E2) { int pos = atomicAdd(&g_cur2[dst2[e]], 1); g_csr2[pos] = src2[e]; }
    }
}

// ================= split-bf16 GEMM via mma.sync, cp.async 2-stage, swizzled ====
#define GK 32
#define TB 8192
#define STG (4 * TB)
#define GSM_TOTAL (2 * STG)

__device__ __forceinline__ void load_chunk(uint32_t sbs,
    const __nv_bfloat16* __restrict__ Ah, const __nv_bfloat16* __restrict__ Al,
    const __nv_bfloat16* __restrict__ Bh, const __nv_bfloat16* __restrict__ Bl,
    int m0, int n0, int M, int K, int kc, int tid)
{
#pragma unroll
    for (int u = 0; u < 2; u++) {
        int c = tid * 2 + u;
        int row = c >> 2, cc = c & 3;
        uint32_t soff = swz((uint32_t)row, (uint32_t)cc * 16);
        int m = m0 + row;
        if (m < M) {
            size_t ga = (size_t)m * K + kc + cc * 8;
            CP16(sbs + soff,      (const char*)(Ah + ga));
            CP16(sbs + TB + soff, (const char*)(Al + ga));
        }
        size_t gb = (size_t)(n0 + row) * K + kc + cc * 8;
        CP16(sbs + 2 * TB + soff, (const char*)(Bh + gb));
        CP16(sbs + 3 * TB + soff, (const char*)(Bl + gb));
    }
}

__global__ void __launch_bounds__(256, 2)
mma_gemm_kernel(const __nv_bfloat16* __restrict__ Ah, const __nv_bfloat16* __restrict__ Al,
                const __nv_bfloat16* __restrict__ Bh, const __nv_bfloat16* __restrict__ Bl,
                int M, int K, int mode,
                float* __restrict__ C,
                __half* __restrict__ feat1, __half* __restrict__ feat2,
                const float* __restrict__ al1v, const float* __restrict__ ar1v,
                const float* __restrict__ al2v, const float* __restrict__ ar2v,
                float* __restrict__ el1, float* __restrict__ er1,
                float* __restrict__ el2, float* __restrict__ er2,
                const float* __restrict__ bias)
{
    extern __shared__ __align__(16) char dsm[];
    __shared__ float sAlv[128], sArv[128];
    __shared__ float sEl[256], sEr[256];

    const uint32_t sb = smem_u32(dsm);
    const int tid = threadIdx.x;
    const int lane = tid & 31;
    const int wid = tid >> 5;
    const int wm = wid >> 2;
    const int wn = wid & 3;
    const int m0 = blockIdx.y * 128, n0 = blockIdx.x * 128;

    const int rel = (n0 >= HD) ? 1 : 0;
    const int ncol0 = n0 & (HD - 1);
    const int h0 = ncol0 >> 6;

    if (mode == 0 && tid < 128) {
        const float* alsel = rel ? al2v : al1v;
        const float* arsel = rel ? ar2v : ar1v;
        sAlv[tid] = alsel[h0 * 64 + tid];
        sArv[tid] = arsel[h0 * 64 + tid];
    }
    sEl[tid] = 0.f; sEr[tid] = 0.f;

    float acc[4][4][4];
#pragma unroll
    for (int i = 0; i < 4; i++)
#pragma unroll
        for (int j = 0; j < 4; j++)
#pragma unroll
            for (int r = 0; r < 4; r++) acc[i][j][r] = 0.f;

    const int a_row = (lane & 15);
    const int a_kof = (lane >> 4) << 3;
    const int b_row = (lane & 7) + ((lane >> 4) << 3);
    const int b_kof = ((lane >> 3) & 1) << 3;

    const int nchunk = K / GK;
    load_chunk(sb, Ah, Al, Bh, Bl, m0, n0, M, K, 0, tid);
    CP_COMMIT();

    for (int c = 0; c < nchunk; c++) {
        if (c + 1 < nchunk)
            load_chunk(sb + ((c + 1) & 1) * STG, Ah, Al, Bh, Bl, m0, n0, M, K, (c + 1) * GK, tid);
        CP_COMMIT();
        CP_WAIT1();
        __syncthreads();

        const uint32_t sbs = sb + (c & 1) * STG;
        const uint32_t sbAh = sbs, sbAl = sbs + TB, sbBh = sbs + 2 * TB, sbBl = sbs + 3 * TB;
#pragma unroll
        for (int k0 = 0; k0 < GK; k0 += 16) {
            uint32_t bh[4][2], bl[4][2];
#pragma unroll
            for (int g = 0; g < 2; g++) {
                int nrow = wn * 32 + g * 16 + b_row;
                uint32_t ba = swz((uint32_t)nrow, (uint32_t)(k0 + b_kof) * 2);
                uint32_t r0, r1, r2, r3;
                LDSM_X4(r0, r1, r2, r3, sbBh + ba);
                bh[g * 2][0] = r0; bh[g * 2][1] = r1;
                bh[g * 2 + 1][0] = r2; bh[g * 2 + 1][1] = r3;
                LDSM_X4(r0, r1, r2, r3, sbBl + ba);
                bl[g * 2][0] = r0; bl[g * 2][1] = r1;
                bl[g * 2 + 1][0] = r2; bl[g * 2 + 1][1] = r3;
            }
#pragma unroll
            for (int im = 0; im < 4; im++) {
                int arow = wm * 64 + im * 16 + a_row;
                uint32_t aa = swz((uint32_t)arow, (uint32_t)(k0 + a_kof) * 2);
                uint32_t ah0, ah1, ah2, ah3, al0, al1, al2, al3;
                LDSM_X4(ah0, ah1, ah2, ah3, sbAh + aa);
                LDSM_X4(al0, al1, al2, al3, sbAl + aa);
#pragma unroll
                for (int in = 0; in < 4; in++) {
                    MMA_16816(acc[im][in], ah0, ah1, ah2, ah3, bh[in][0], bh[in][1]);
                    MMA_16816(acc[im][in], ah0, ah1, ah2, ah3, bl[in][0], bl[in][1]);
                    MMA_16816(acc[im][in], al0, al1, al2, al3, bh[in][0], bh[in][1]);
                }
            }
        }
        __syncthreads();
    }

    // ---- epilogue ----
    if (mode == 0) {
        __half* Cf = rel ? feat2 : feat1;
        const int hl = wn >> 1;
#pragma unroll
        for (int im = 0; im < 4; im++) {
            int r0l = wm * 64 + im * 16 + (lane >> 2);
            float e0 = 0.f, e1 = 0.f, q0 = 0.f, q1 = 0.f;
#pragma unroll
            for (int in = 0; in < 4; in++) {
                int ct = wn * 32 + in * 8 + (lane & 3) * 2;
                float a0 = sAlv[ct], a1 = sAlv[ct + 1];
                float p0 = sArv[ct], p1 = sArv[ct + 1];
                e0 += acc[im][in][0] * a0 + acc[im][in][1] * a1;
                q0 += acc[im][in][0] * p0 + acc[im][in][1] * p1;
                e1 += acc[im][in][2] * a0 + acc[im][in][3] * a1;
                q1 += acc[im][in][2] * p0 + acc[im][in][3] * p1;

                int row0 = m0 + r0l;
                int col  = ncol0 + ct;
                if (row0 < M)
                    *(__half2*)(Cf + (size_t)row0 * HD + col) =
                        __floats2half2_rn(acc[im][in][0], acc[im][in][1]);
                if (row0 + 8 < M)
                    *(__half2*)(Cf + (size_t)(row0 + 8) * HD + col) =
                        __floats2half2_rn(acc[im][in][2], acc[im][in][3]);
            }
            atomicAdd(&sEl[r0l * 2 + hl], e0);
            atomicAdd(&sEr[r0l * 2 + hl], q0);
            atomicAdd(&sEl[(r0l + 8) * 2 + hl], e1);
            atomicAdd(&sEr[(r0l + 8) * 2 + hl], q1);
        }
        __syncthreads();
        if (tid < 128) {
            int m = m0 + tid;
            if (m < M) {
                float* elo = rel ? el2 : el1;
                float* ero = rel ? er2 : er1;
                elo[(size_t)m * HH + h0 + 0] = sEl[tid * 2 + 0];
                elo[(size_t)m * HH + h0 + 1] = sEl[tid * 2 + 1];
                ero[(size_t)m * HH + h0 + 0] = sEr[tid * 2 + 0];
                ero[(size_t)m * HH + h0 + 1] = sEr[tid * 2 + 1];
            }
        }
    } else {
#pragma unroll
        for (int im = 0; im < 4; im++) {
#pragma unroll
            for (int in = 0; in < 4; in++) {
                int row0 = m0 + wm * 64 + im * 16 + (lane >> 2);
                int col  = n0 + wn * 32 + in * 8 + (lane & 3) * 2;
                float bx = bias[col], by = bias[col + 1];
                if (row0 < M)
                    *(float2*)(C + (size_t)row0 * HD + col) =
                        make_float2(acc[im][in][0] + bx, acc[im][in][1] + by);
                if (row0 + 8 < M)
                    *(float2*)(C + (size_t)(row0 + 8) * HD + col) =
                        make_float2(acc[im][in][2] + bx, acc[im][in][3] + by);
            }
        }
    }
}

// ================= fused GAT aggregate: warp per dst node, 2 passes, fp16 gather ====
__global__ void gat_aggregate_kernel(const float* __restrict__ b1v,
                                     const float* __restrict__ b2v, int Nn)
{
    int n = (blockIdx.x * blockDim.x + threadIdx.x) >> 5;
    int lane = threadIdx.x & 31;
    if (n >= Nn) return;
    const int relv = blockIdx.y;
    const int* off = relv ? g_off2 : g_off1;
    const int* csr = relv ? g_csr2 : g_csr1;
    const float* el = relv ? g_el2 : g_el1;
    const float* er = relv ? g_er2 : g_er1;
    const __half* feat = relv ? g_feat2 : g_feat1;
    const float* bias = relv ? b2v : b1v;
    const int rel_off = relv ? HD : 0;

    const int beg = off[n], end = off[n + 1];
    float4 er4 = *(const float4*)(er + n * HH);

    // pass 1: denom (no max subtraction; |e| small so exp is safe)
    float4 ds = make_float4(0.f, 0.f, 0.f, 0.f);
    for (int k = beg + lane; k < end; k += 32) {
        int s = csr[k];
        float4 l = *(const float4*)(el + s * HH);
        float4 e;
        e.x = l.x + er4.x; e.x = e.x > 0.f ? e.x : NEG_SLOPE * e.x;
        e.y = l.y + er4.y; e.y = e.y > 0.f ? e.y : NEG_SLOPE * e.y;
        e.z = l.z + er4.z; e.z = e.z > 0.f ? e.z : NEG_SLOPE * e.z;
        e.w = l.w + er4.w; e.w = e.w > 0.f ? e.w : NEG_SLOPE * e.w;
        ds.x += __expf(e.x); ds.y += __expf(e.y);
        ds.z += __expf(e.z); ds.w += __expf(e.w);
    }
#pragma unroll
    for (int o = 16; o; o >>= 1) {
        ds.x += __shfl_xor_sync(0xffffffffu, ds.x, o);
        ds.y += __shfl_xor_sync(0xffffffffu, ds.y, o);
        ds.z += __shfl_xor_sync(0xffffffffu, ds.z, o);
        ds.w += __shfl_xor_sync(0xffffffffu, ds.w, o);
    }

    const int head = lane >> 3;
    const float dh   = head == 0 ? ds.x : head == 1 ? ds.y : head == 2 ? ds.z : ds.w;
    const float erh  = head == 0 ? er4.x: head == 1 ? er4.y: head == 2 ? er4.z: er4.w;
    const float invd = 1.0f / dh;

    float acc[8];
#pragma unroll
    for (int i = 0; i < 8; i++) acc[i] = 0.f;

    // pass 2: weighted fp16 gather, deeper MLP via unroll 4
    for (int base = beg; base < end; base += 32) {
        int myidx = (base + lane < end) ? csr[base + lane] : 0;
        int cnt = min(32, end - base);
#pragma unroll 4
        for (int j = 0; j < cnt; j++) {
            int s = __shfl_sync(0xffffffffu, myidx, j);
            float e = el[s * HH + head] + erh;
            e = e > 0.f ? e : NEG_SLOPE * e;
            float alpha = __expf(e) * invd;
            uint4 raw = *(const uint4*)(feat + (size_t)s * HD + lane * 8);
            float2 f0 = __half22float2(*(__half2*)&raw.x);
            float2 f1 = __half22float2(*(__half2*)&raw.y);
            float2 f2 = __half22float2(*(__half2*)&raw.z);
            float2 f3 = __half22float2(*(__half2*)&raw.w);
            acc[0] = fmaf(f0.x, alpha, acc[0]);
            acc[1] = fmaf(f0.y, alpha, acc[1]);
            acc[2] = fmaf(f1.x, alpha, acc[2]);
            acc[3] = fmaf(f1.y, alpha, acc[3]);
            acc[4] = fmaf(f2.x, alpha, acc[4]);
            acc[5] = fmaf(f2.y, alpha, acc[5]);
            acc[6] = fmaf(f3.x, alpha, acc[6]);
            acc[7] = fmaf(f3.y, alpha, acc[7]);
        }
    }

    float4 bo0 = *(const float4*)(bias + lane * 8);
    float4 bo1 = *(const float4*)(bias + lane * 8 + 4);
    float w[8];
    w[0] = acc[0] + bo0.x; w[1] = acc[1] + bo0.y; w[2] = acc[2] + bo0.z; w[3] = acc[3] + bo0.w;
    w[4] = acc[4] + bo1.x; w[5] = acc[5] + bo1.y; w[6] = acc[6] + bo1.z; w[7] = acc[7] + bo1.w;

    __align__(16) __nv_bfloat16 hb[8], lb[8];
#pragma unroll
    for (int i = 0; i < 8; i++) {
        hb[i] = __float2bfloat16(w[i]);
        lb[i] = __float2bfloat16(w[i] - __bfloat162float(hb[i]));
    }
    size_t didx = (size_t)n * HD2 + rel_off + lane * 8;
    *(uint4*)(g_semh + didx) = *(uint4*)hb;
    *(uint4*)(g_seml + didx) = *(uint4*)lb;
}

// ================= launch =================
static inline int ceil_div(int a, int b) { return (a + b - 1) / b; }

extern "C" void kernel_launch(void* const* d_in, const int* in_sizes, int n_in,
                              void* d_out, int out_size)
{
    const float* h    = (const float*)d_in[0];
    const float* Wg1  = (const float*)d_in[1];
    const float* al1  = (const float*)d_in[2];
    const float* ar1  = (const float*)d_in[3];
    const float* b1   = (const float*)d_in[4];
    const float* Wg2  = (const float*)d_in[5];
    const float* al2  = (const float*)d_in[6];
    const float* ar2  = (const float*)d_in[7];
    const float* b2   = (const float*)d_in[8];
    const float* Wfc  = (const float*)d_in[9];
    const float* bfc  = (const float*)d_in[10];
    const int*   src1 = (const int*)d_in[11];
    const int*   dst1 = (const int*)d_in[12];
    const int*   src2 = (const int*)d_in[13];
    const int*   dst2 = (const int*)d_in[14];
    float* out = (float*)d_out;

    const int Nn = in_sizes[0] / IN_F;
    const int E1 = in_sizes[11];
    const int E2 = in_sizes[13];

    __half *feat1, *feat2;
    float *el1, *er1, *el2, *er2;
    __nv_bfloat16 *hhi, *hlo, *semh, *seml, *wgh, *wgl, *wfch, *wfcl;
    cudaGetSymbolAddress((void**)&feat1, g_feat1);
    cudaGetSymbolAddress((void**)&feat2, g_feat2);
    cudaGetSymbolAddress((void**)&el1,   g_el1);
    cudaGetSymbolAddress((void**)&er1,   g_er1);
    cudaGetSymbolAddress((void**)&el2,   g_el2);
    cudaGetSymbolAddress((void**)&er2,   g_er2);
    cudaGetSymbolAddress((void**)&hhi,   g_h_hi);
    cudaGetSymbolAddress((void**)&hlo,   g_h_lo);
    cudaGetSymbolAddress((void**)&semh,  g_semh);
    cudaGetSymbolAddress((void**)&seml,  g_seml);
    cudaGetSymbolAddress((void**)&wgh,   g_wgh);
    cudaGetSymbolAddress((void**)&wgl,   g_wgl);
    cudaGetSymbolAddress((void**)&wfch,  g_wfch);
    cudaGetSymbolAddress((void**)&wfcl,  g_wfcl);

    cudaFuncSetAttribute(mma_gemm_kernel, cudaFuncAttributeMaxDynamicSharedMemorySize, GSM_TOTAL);

    // --- K1: zero counts + weight splits ---
    const int ZB = ceil_div(Nn, 256);
    pre1_kernel<<<ZB + 64 + 64 + 128, 256>>>(Wg1, Wg2, Wfc, Nn, ZB);

    // --- K2: h split + both hists ---
    const int HB = Nn * IN_F / 4 / 256;
    const int H1B = ceil_div(E1, 256);
    const int H2B = ceil_div(E2, 256);
    pre2_kernel<<<HB + H1B + H2B, 256>>>(h, dst1, dst2, HB, E1, E2, H1B);

    // --- scan chain (R9-proven) ---
    const int nb = ceil_div(Nn, 1024);
    {
        dim3 g(nb, 2);
        partial_kernel<<<g, 256>>>(Nn);
        top_scan_kernel<<<2, 32>>>(nb);
        final_scan_kernel<<<g, 256>>>(Nn, E1, E2);
    }
    // --- fill ---
    {
        const int Emax = E1 > E2 ? E1 : E2;
        dim3 g(ceil_div(Emax, 256), 2);
        fill_kernel<<<g, 256>>>(src1, dst1, src2, dst2, E1, E2);
    }

    // --- fused projection GEMM (both relations), el/er in epilogue ---
    {
        dim3 grid(4, ceil_div(Nn, 128));
        mma_gemm_kernel<<<grid, 256, GSM_TOTAL>>>(hhi, hlo, wgh, wgl, Nn, IN_F, 0,
                                                  nullptr, feat1, feat2,
                                                  al1, ar1, al2, ar2,
                                                  el1, er1, el2, er2, nullptr);
    }
    // --- fused softmax + aggregate ---
    {
        dim3 grid(ceil_div(Nn * 32, 256), 2);
        gat_aggregate_kernel<<<grid, 256>>>(b1, b2, Nn);
    }
    // --- FC GEMM ---
    {
        dim3 grid(2, ceil_div(Nn, 128));
        mma_gemm_kernel<<<grid, 256, GSM_TOTAL>>>(semh, seml, wfch, wfcl, Nn, HD2, 1,
                                                  out, nullptr, nullptr,
                                                  nullptr, nullptr, nullptr, nullptr,
                                                  nullptr, nullptr, nullptr, nullptr, bfc);
    }
}